// round 9
// baseline (speedup 1.0000x reference)
#include <cuda_runtime.h>
#include <cstdint>

#define D_MODEL 1024
#define SEQ     2048
#define BATCH   2
#define NHEAD   16
#define DK      64
#define MTOT    (BATCH * SEQ)

// Scratch (allocation-free rule)
__device__ float g_Q[BATCH * SEQ * D_MODEL];
__device__ float g_K[BATCH * SEQ * D_MODEL];
__device__ float g_V[BATCH * SEQ * D_MODEL];
__device__ float g_att[BATCH * SEQ * D_MODEL];
__device__ uint32_t g_Axp[MTOT * D_MODEL];          // packed x (A-layout)
__device__ uint32_t g_Aop[MTOT * D_MODEL];          // packed att (A-layout)
__device__ uint32_t g_Wp[4 * D_MODEL * D_MODEL];    // packed weights (B-layout)

// ---------------------------------------------------------------------------
__device__ __forceinline__ uint32_t f2tf(float f) {
    uint32_t u;
    asm("cvt.rna.tf32.f32 %0, %1;" : "=r"(u) : "f"(f));
    return u;
}

__device__ __forceinline__ void mma_tf32(float* d, const uint32_t* a,
                                         const uint32_t* b, const float* c) {
    asm volatile(
        "mma.sync.aligned.m16n8k8.row.col.f32.tf32.tf32.f32 "
        "{%0,%1,%2,%3}, {%4,%5,%6,%7}, {%8,%9}, {%10,%11,%12,%13};\n"
        : "=f"(d[0]), "=f"(d[1]), "=f"(d[2]), "=f"(d[3])
        : "r"(a[0]), "r"(a[1]), "r"(a[2]), "r"(a[3]),
          "r"(b[0]), "r"(b[1]),
          "f"(c[0]), "f"(c[1]), "f"(c[2]), "f"(c[3]));
}

// ---------------------------------------------------------------------------
// Pack kernels: row-major fp32 -> tf32 in mma-fragment order.
// Panel = 128 rows(cols) x 16 k = 2048 uint32.
// A idx bits: kk(1)|wr(2)|mt(1)|lane(5)|rr(2), rr = rhi + 2*khi
//   m = 128*mtile + 32*wr + 16*mt + 8*rhi + gid,  k = 16*kst + 8*kk + 4*khi + tig
// B idx bits: kk(1)|wc(1)|ntp(2)|lane(5)|rr(2), rr = khi + 2*nlo
//   n = 128*ntile + 64*wc + 8*(2*ntp+nlo) + gid,  k = 16*kst + 8*kk + 4*khi + tig
// ---------------------------------------------------------------------------
__global__ __launch_bounds__(256)
void pack_A_kernel(const float* __restrict__ src, uint32_t* __restrict__ dst) {
    const int total = MTOT * D_MODEL;
    for (int i = blockIdx.x * blockDim.x + threadIdx.x; i < total;
         i += gridDim.x * blockDim.x) {
        int panel = i >> 11, idx = i & 2047;
        int mtile = panel >> 6, kst = panel & 63;
        int kk = idx >> 10, rem = idx & 1023;
        int wr = rem >> 8; rem &= 255;
        int mt = rem >> 7; rem &= 127;
        int q = rem >> 2, rr = rem & 3;
        int gid = q >> 2, tig = q & 3;
        int rhi = rr & 1, khi = rr >> 1;
        int m = mtile * 128 + wr * 32 + mt * 16 + rhi * 8 + gid;
        int k = kst * 16 + kk * 8 + khi * 4 + tig;
        dst[i] = f2tf(src[(size_t)m * D_MODEL + k]);
    }
}

__global__ __launch_bounds__(256)
void pack_B_kernel(const float* __restrict__ W0, const float* __restrict__ W1,
                   const float* __restrict__ W2, const float* __restrict__ W3,
                   uint32_t* __restrict__ dst) {
    const int z = blockIdx.y;
    const float* W = (z == 0) ? W0 : (z == 1) ? W1 : (z == 2) ? W2 : W3;
    uint32_t* out = dst + (size_t)z * D_MODEL * D_MODEL;
    const int total = D_MODEL * D_MODEL;
    for (int i = blockIdx.x * blockDim.x + threadIdx.x; i < total;
         i += gridDim.x * blockDim.x) {
        int panel = i >> 11, idx = i & 2047;
        int ntile = panel >> 6, kst = panel & 63;
        int kk = idx >> 10, rem = idx & 1023;
        int wc = rem >> 9; rem &= 511;
        int ntp = rem >> 7; rem &= 127;
        int q = rem >> 2, rr = rem & 3;
        int gid = q >> 2, tig = q & 3;
        int khi = rr & 1, nlo = rr >> 1;
        int n = ntile * 128 + wc * 64 + (2 * ntp + nlo) * 8 + gid;
        int k = kst * 16 + kk * 8 + khi * 4 + tig;
        out[i] = f2tf(W[(size_t)k * D_MODEL + n]);
    }
}

// ---------------------------------------------------------------------------
// Packed TF32 GEMM: 128x128 tile, KC=16, R3-proven ldg->reg->sts double
// buffer (no cp.async). 256 threads = 8 warps (4 wr x 2 wc), warp 32x64.
// Producer/stage: 4 LDG.128 + 4 STS.128 per thread, zero cvt.
// Consumer per K=8 chunk: 6 LDS.128 + 16 mma.
// ---------------------------------------------------------------------------
#define KSTAGES 64
#define PANEL   2048

__device__ __forceinline__ void gemm_packed_body(
    const uint32_t* __restrict__ Ap,   // + mtile*KSTAGES*PANEL
    const uint32_t* __restrict__ Bp,   // + ntile*KSTAGES*PANEL
    float* __restrict__ C, int bm, int bn, int N) {
    __shared__ uint32_t smb[2][2 * PANEL];   // [buf][A(2048) | B(2048)]

    const int tid = threadIdx.x;
    const int w = tid >> 5, lane = tid & 31;
    const int wr = w >> 1, wc = w & 1;
    const int gid = lane >> 2, tig = lane & 3;

    float acc[2][8][4] = {};
    uint4 ar[2], br[2];

    auto ldg_stage = [&](int ks) {
        const uint32_t* ga = Ap + ks * PANEL;
        const uint32_t* gb = Bp + ks * PANEL;
#pragma unroll
        for (int i = 0; i < 2; i++) {
            ar[i] = *(const uint4*)(ga + (i * 256 + tid) * 4);
            br[i] = *(const uint4*)(gb + (i * 256 + tid) * 4);
        }
    };
    auto sts_stage = [&](int b) {
#pragma unroll
        for (int i = 0; i < 2; i++) {
            *(uint4*)&smb[b][(i * 256 + tid) * 4] = ar[i];
            *(uint4*)&smb[b][PANEL + (i * 256 + tid) * 4] = br[i];
        }
    };

    ldg_stage(0);
    sts_stage(0);
    __syncthreads();

    int buf = 0;
    for (int ks = 0; ks < KSTAGES; ks++, buf ^= 1) {
        const bool more = (ks + 1) < KSTAGES;
        if (more) ldg_stage(ks + 1);

        const uint32_t* sA = smb[buf];
        const uint32_t* sB = smb[buf] + PANEL;
#pragma unroll
        for (int kk = 0; kk < 2; kk++) {
            uint32_t af[2][4];
            *(uint4*)af[0] = *(const uint4*)(sA + kk * 1024 + wr * 256 + lane * 4);
            *(uint4*)af[1] = *(const uint4*)(sA + kk * 1024 + wr * 256 + 128 + lane * 4);
            uint32_t bq[4][4];
#pragma unroll
            for (int ntp = 0; ntp < 4; ntp++)
                *(uint4*)bq[ntp] =
                    *(const uint4*)(sB + kk * 1024 + wc * 512 + ntp * 128 + lane * 4);
#pragma unroll
            for (int mt = 0; mt < 2; mt++)
#pragma unroll
                for (int ntp = 0; ntp < 4; ntp++) {
                    mma_tf32(acc[mt][2 * ntp], af[mt], &bq[ntp][0], acc[mt][2 * ntp]);
                    mma_tf32(acc[mt][2 * ntp + 1], af[mt], &bq[ntp][2],
                             acc[mt][2 * ntp + 1]);
                }
        }

        if (more) {
            sts_stage(buf ^ 1);
            __syncthreads();
        }
    }

#pragma unroll
    for (int mt = 0; mt < 2; mt++)
#pragma unroll
        for (int nt = 0; nt < 8; nt++) {
            int row = bm + wr * 32 + mt * 16 + gid;
            int col = bn + wc * 64 + nt * 8 + 2 * tig;
            *(float2*)(C + (size_t)row * N + col) =
                make_float2(acc[mt][nt][0], acc[mt][nt][1]);
            *(float2*)(C + (size_t)(row + 8) * N + col) =
                make_float2(acc[mt][nt][2], acc[mt][nt][3]);
        }
}

__global__ __launch_bounds__(256)
void gemm_qkv_packed(const uint32_t* __restrict__ Axp,
                     const uint32_t* __restrict__ Wp) {
    float* C = (blockIdx.z == 0) ? g_Q : (blockIdx.z == 1) ? g_K : g_V;
    gemm_packed_body(Axp + (size_t)blockIdx.y * KSTAGES * PANEL,
                     Wp + (size_t)blockIdx.z * D_MODEL * D_MODEL
                        + (size_t)blockIdx.x * KSTAGES * PANEL,
                     C, blockIdx.y * 128, blockIdx.x * 128, D_MODEL);
}

__global__ __launch_bounds__(256)
void gemm_o_packed(const uint32_t* __restrict__ Aop,
                   const uint32_t* __restrict__ Wp, float* __restrict__ C) {
    gemm_packed_body(Aop + (size_t)blockIdx.y * KSTAGES * PANEL,
                     Wp + (size_t)3 * D_MODEL * D_MODEL
                        + (size_t)blockIdx.x * KSTAGES * PANEL,
                     C, blockIdx.y * 128, blockIdx.x * 128, D_MODEL);
}

// ---------------------------------------------------------------------------
// Flash attention, TF32 mma.sync (proven 583.8us version, unchanged).
// ---------------------------------------------------------------------------
#define QS_STRIDE 68
#define VS_STRIDE 72
#define SM_Q 0
#define SM_K (128 * QS_STRIDE)
#define SM_V (SM_K + 64 * QS_STRIDE)
#define ATTN_SMEM_UINTS (SM_V + 64 * VS_STRIDE)
#define ATTN_SMEM_BYTES (ATTN_SMEM_UINTS * 4)

__global__ __launch_bounds__(256)
void attn_kernel(const float* __restrict__ Q, const float* __restrict__ K,
                 const float* __restrict__ V, float* __restrict__ O) {
    extern __shared__ uint32_t sm[];
    uint32_t* Qs = sm + SM_Q;
    uint32_t* Ps = sm + SM_Q;   // aliased: Qs dead after fragment hoist
    uint32_t* Ks = sm + SM_K;
    uint32_t* Vs = sm + SM_V;

    const int qt = blockIdx.x, h = blockIdx.y, b = blockIdx.z;
    const int tid = threadIdx.x;
    const int w = tid >> 5, lane = tid & 31;
    const int gid = lane >> 2, tig = lane & 3;

    const float* Qbase = Q + ((size_t)b * SEQ + qt * 128) * D_MODEL + h * DK;
    const float* Kbase = K + (size_t)b * SEQ * D_MODEL + h * DK;
    const float* Vbase = V + (size_t)b * SEQ * D_MODEL + h * DK;

#pragma unroll
    for (int i = 0; i < 8; i++) {
        int idx = i * 256 + tid;
        int r = idx >> 4, c = (idx & 15) * 4;
        float4 v = *(const float4*)(Qbase + (size_t)r * D_MODEL + c);
        *(uint4*)&Qs[r * QS_STRIDE + c] =
            make_uint4(f2tf(v.x), f2tf(v.y), f2tf(v.z), f2tf(v.w));
    }
    __syncthreads();

    const int r0 = w * 16 + gid;
    uint32_t qf[8][4];
#pragma unroll
    for (int kc = 0; kc < 8; kc++) {
        qf[kc][0] = Qs[r0 * QS_STRIDE + kc * 8 + tig];
        qf[kc][1] = Qs[(r0 + 8) * QS_STRIDE + kc * 8 + tig];
        qf[kc][2] = Qs[r0 * QS_STRIDE + kc * 8 + tig + 4];
        qf[kc][3] = Qs[(r0 + 8) * QS_STRIDE + kc * 8 + tig + 4];
    }

    float o[8][4] = {};
    float m0 = -1e30f, m1 = -1e30f, l0 = 0.f, l1 = 0.f;

    for (int kt = 0; kt < SEQ / 64; kt++) {
        __syncthreads();
        const float* kb = Kbase + (size_t)kt * 64 * D_MODEL;
        const float* vb = Vbase + (size_t)kt * 64 * D_MODEL;
#pragma unroll
        for (int i = 0; i < 4; i++) {
            int idx = i * 256 + tid;
            int r = idx >> 4, c = (idx & 15) * 4;
            float4 k4 = *(const float4*)(kb + (size_t)r * D_MODEL + c);
            *(uint4*)&Ks[r * QS_STRIDE + c] =
                make_uint4(f2tf(k4.x), f2tf(k4.y), f2tf(k4.z), f2tf(k4.w));
            float4 v4 = *(const float4*)(vb + (size_t)r * D_MODEL + c);
            *(uint4*)&Vs[r * VS_STRIDE + c] =
                make_uint4(f2tf(v4.x), f2tf(v4.y), f2tf(v4.z), f2tf(v4.w));
        }
        __syncthreads();

        float s[8][4] = {};
#pragma unroll
        for (int kc = 0; kc < 8; kc++) {
#pragma unroll
            for (int nt = 0; nt < 8; nt++) {
                uint32_t kf[2];
                int kvp = nt * 8 + gid;
                kf[0] = Ks[kvp * QS_STRIDE + kc * 8 + tig];
                kf[1] = Ks[kvp * QS_STRIDE + kc * 8 + tig + 4];
                mma_tf32(s[nt], qf[kc], kf, s[nt]);
            }
        }

        const float scale = 0.125f;
        float mx0 = -1e30f, mx1 = -1e30f;
#pragma unroll
        for (int nt = 0; nt < 8; nt++) {
#pragma unroll
            for (int i = 0; i < 4; i++) s[nt][i] *= scale;
            mx0 = fmaxf(mx0, fmaxf(s[nt][0], s[nt][1]));
            mx1 = fmaxf(mx1, fmaxf(s[nt][2], s[nt][3]));
        }
        mx0 = fmaxf(mx0, __shfl_xor_sync(0xffffffffu, mx0, 1));
        mx0 = fmaxf(mx0, __shfl_xor_sync(0xffffffffu, mx0, 2));
        mx1 = fmaxf(mx1, __shfl_xor_sync(0xffffffffu, mx1, 1));
        mx1 = fmaxf(mx1, __shfl_xor_sync(0xffffffffu, mx1, 2));

        float nm0 = fmaxf(m0, mx0), nm1 = fmaxf(m1, mx1);
        float corr0 = __expf(m0 - nm0), corr1 = __expf(m1 - nm1);
        m0 = nm0; m1 = nm1;

        float rs0 = 0.f, rs1 = 0.f;
#pragma unroll
        for (int nt = 0; nt < 8; nt++) {
            float p0 = __expf(s[nt][0] - nm0);
            float p1 = __expf(s[nt][1] - nm0);
            float p2 = __expf(s[nt][2] - nm1);
            float p3 = __expf(s[nt][3] - nm1);
            rs0 += p0 + p1;
            rs1 += p2 + p3;
            int col = nt * 8 + 2 * tig;
            *(uint2*)&Ps[r0 * QS_STRIDE + col] = make_uint2(f2tf(p0), f2tf(p1));
            *(uint2*)&Ps[(r0 + 8) * QS_STRIDE + col] = make_uint2(f2tf(p2), f2tf(p3));
        }
        rs0 += __shfl_xor_sync(0xffffffffu, rs0, 1);
        rs0 += __shfl_xor_sync(0xffffffffu, rs0, 2);
        rs1 += __shfl_xor_sync(0xffffffffu, rs1, 1);
        rs1 += __shfl_xor_sync(0xffffffffu, rs1, 2);
        l0 = l0 * corr0 + rs0;
        l1 = l1 * corr1 + rs1;

#pragma unroll
        for (int nt = 0; nt < 8; nt++) {
            o[nt][0] *= corr0; o[nt][1] *= corr0;
            o[nt][2] *= corr1; o[nt][3] *= corr1;
        }
        __syncwarp();

#pragma unroll
        for (int kc = 0; kc < 8; kc++) {
            uint32_t pa[4];
            pa[0] = Ps[r0 * QS_STRIDE + kc * 8 + tig];
            pa[1] = Ps[(r0 + 8) * QS_STRIDE + kc * 8 + tig];
            pa[2] = Ps[r0 * QS_STRIDE + kc * 8 + tig + 4];
            pa[3] = Ps[(r0 + 8) * QS_STRIDE + kc * 8 + tig + 4];
#pragma unroll
            for (int nt = 0; nt < 8; nt++) {
                uint32_t vf[2];
                vf[0] = Vs[(kc * 8 + tig) * VS_STRIDE + nt * 8 + gid];
                vf[1] = Vs[(kc * 8 + tig + 4) * VS_STRIDE + nt * 8 + gid];
                mma_tf32(o[nt], pa, vf, o[nt]);
            }
        }
    }

    float inv0 = 1.0f / l0, inv1 = 1.0f / l1;
    float* obase = O + ((size_t)b * SEQ + qt * 128) * D_MODEL + h * DK;
#pragma unroll
    for (int nt = 0; nt < 8; nt++) {
        int col = nt * 8 + 2 * tig;
        *(float2*)(obase + (size_t)r0 * D_MODEL + col) =
            make_float2(o[nt][0] * inv0, o[nt][1] * inv0);
        *(float2*)(obase + (size_t)(r0 + 8) * D_MODEL + col) =
            make_float2(o[nt][2] * inv1, o[nt][3] * inv1);
    }
}

// ---------------------------------------------------------------------------
extern "C" void kernel_launch(void* const* d_in, const int* in_sizes, int n_in,
                              void* d_out, int out_size) {
    const float* x  = (const float*)d_in[0];
    const float* Wq = (const float*)d_in[1];
    const float* Wk = (const float*)d_in[2];
    const float* Wv = (const float*)d_in[3];
    const float* Wo = (const float*)d_in[4];
    float* out = (float*)d_out;

    float *Qp, *Kp, *Vp, *Ap;
    uint32_t *Axp, *Aop, *Wp;
    cudaGetSymbolAddress((void**)&Qp, g_Q);
    cudaGetSymbolAddress((void**)&Kp, g_K);
    cudaGetSymbolAddress((void**)&Vp, g_V);
    cudaGetSymbolAddress((void**)&Ap, g_att);
    cudaGetSymbolAddress((void**)&Axp, g_Axp);
    cudaGetSymbolAddress((void**)&Aop, g_Aop);
    cudaGetSymbolAddress((void**)&Wp, g_Wp);

    // Pack weights (B-layout) and x (A-layout)
    pack_B_kernel<<<dim3(1024, 4), 256>>>(Wq, Wk, Wv, Wo, Wp);
    pack_A_kernel<<<4096, 256>>>(x, Axp);

    // QKV projections
    gemm_qkv_packed<<<dim3(8, 32, 3), 256>>>(Axp, Wp);

    // Attention
    cudaFuncSetAttribute(attn_kernel, cudaFuncAttributeMaxDynamicSharedMemorySize,
                         ATTN_SMEM_BYTES);
    attn_kernel<<<dim3(SEQ / 128, NHEAD, BATCH), 256, ATTN_SMEM_BYTES>>>(Qp, Kp, Vp, Ap);

    // Pack attention output, then output projection
    pack_A_kernel<<<4096, 256>>>(Ap, Aop);
    gemm_o_packed<<<dim3(8, 32, 1), 256>>>(Aop, Wp, out);
}

// round 10
// speedup vs baseline: 1.5600x; 1.5600x over previous
#include <cuda_runtime.h>
#include <cuda_fp16.h>
#include <cstdint>

#define D_MODEL 1024
#define SEQ     2048
#define BATCH   2
#define NHEAD   16
#define DK      64
#define MTOT    (BATCH * SEQ)

// Scratch (allocation-free rule)
__device__ float g_Q[BATCH * SEQ * D_MODEL];
__device__ float g_K[BATCH * SEQ * D_MODEL];
__device__ float g_V[BATCH * SEQ * D_MODEL];
__device__ float g_att[BATCH * SEQ * D_MODEL];
__device__ uint32_t g_Wth[4 * D_MODEL * D_MODEL / 2];  // W^T as fp16 pairs

// ---------------------------------------------------------------------------
__device__ __forceinline__ uint32_t f2tf(float f) {
    uint32_t u;
    asm("cvt.rna.tf32.f32 %0, %1;" : "=r"(u) : "f"(f));
    return u;
}
__device__ __forceinline__ uint32_t f2h2(float lo, float hi) {
    uint32_t r;
    asm("cvt.rn.f16x2.f32 %0, %2, %1;" : "=r"(r) : "f"(lo), "f"(hi));
    return r;
}

__device__ __forceinline__ void mma_tf32(float* d, const uint32_t* a,
                                         const uint32_t* b, const float* c) {
    asm volatile(
        "mma.sync.aligned.m16n8k8.row.col.f32.tf32.tf32.f32 "
        "{%0,%1,%2,%3}, {%4,%5,%6,%7}, {%8,%9}, {%10,%11,%12,%13};\n"
        : "=f"(d[0]), "=f"(d[1]), "=f"(d[2]), "=f"(d[3])
        : "r"(a[0]), "r"(a[1]), "r"(a[2]), "r"(a[3]),
          "r"(b[0]), "r"(b[1]),
          "f"(c[0]), "f"(c[1]), "f"(c[2]), "f"(c[3]));
}

__device__ __forceinline__ void mma_f16(float* d, const uint32_t* a,
                                        const uint32_t* b, const float* c) {
    asm volatile(
        "mma.sync.aligned.m16n8k16.row.col.f32.f16.f16.f32 "
        "{%0,%1,%2,%3}, {%4,%5,%6,%7}, {%8,%9}, {%10,%11,%12,%13};\n"
        : "=f"(d[0]), "=f"(d[1]), "=f"(d[2]), "=f"(d[3])
        : "r"(a[0]), "r"(a[1]), "r"(a[2]), "r"(a[3]),
          "r"(b[0]), "r"(b[1]),
          "f"(c[0]), "f"(c[1]), "f"(c[2]), "f"(c[3]));
}

// ---------------------------------------------------------------------------
// Transpose + cvt: g_Wth[z][n][k] = fp16(W_z[k][n]), packed 2 halfs/u32.
// ---------------------------------------------------------------------------
__global__ __launch_bounds__(256)
void transpose_h_kernel(const float* __restrict__ Wq, const float* __restrict__ Wk,
                        const float* __restrict__ Wv, const float* __restrict__ Wo,
                        uint32_t* __restrict__ Wth) {
    __shared__ float tile[32][33];
    const float* W = (blockIdx.z == 0) ? Wq : (blockIdx.z == 1) ? Wk
                   : (blockIdx.z == 2) ? Wv : Wo;
    uint32_t* T = Wth + (size_t)blockIdx.z * D_MODEL * (D_MODEL / 2);
    int tx = threadIdx.x, ty = threadIdx.y;
    int x = blockIdx.x * 32 + tx;
#pragma unroll
    for (int i = 0; i < 4; i++)
        tile[ty + i * 8][tx] = W[(size_t)(blockIdx.y * 32 + ty + i * 8) * D_MODEL + x];
    __syncthreads();
    // write rows n = blockIdx.x*32 + (ty+i*8), k pairs from blockIdx.y*32 + 2*tx
    int kp = blockIdx.y * 16 + tx;   // u32 (half-pair) column; tx<16 handles pairs
    if (tx < 16) {
#pragma unroll
        for (int i = 0; i < 4; i++) {
            int n = blockIdx.x * 32 + ty + i * 8;
            float lo = tile[tx * 2][ty + i * 8];
            float hi = tile[tx * 2 + 1][ty + i * 8];
            T[(size_t)n * (D_MODEL / 2) + kp] = f2h2(lo, hi);
        }
    } else {
#pragma unroll
        for (int i = 0; i < 4; i++) {
            int n = blockIdx.x * 32 + ty + i * 8;
            int t2 = tx - 16;
            float lo = tile[t2 * 2 + 16? 0 : 0][0];  // placeholder (never used)
            (void)lo; (void)n; (void)t2;
        }
    }
    // second half of k pairs (tx >= 16 handled here to keep all 32 lanes busy)
    if (tx >= 16) {
        int t2 = tx - 16;
        int kp2 = blockIdx.y * 16 + t2;
#pragma unroll
        for (int i = 0; i < 4; i++) {
            int n = blockIdx.x * 32 + ty + i * 8 ;
            // lanes 16-31 duplicate nothing: cover same pairs via second sweep? No-op.
            (void)kp2; (void)n;
        }
    }
}

// NOTE: simpler, conflict-free full-coverage variant used instead below.
__global__ __launch_bounds__(256)
void transpose_h2_kernel(const float* __restrict__ Wq, const float* __restrict__ Wk,
                         const float* __restrict__ Wv, const float* __restrict__ Wo,
                         uint32_t* __restrict__ Wth) {
    __shared__ float tile[32][33];
    const float* W = (blockIdx.z == 0) ? Wq : (blockIdx.z == 1) ? Wk
                   : (blockIdx.z == 2) ? Wv : Wo;
    uint32_t* T = Wth + (size_t)blockIdx.z * D_MODEL * (D_MODEL / 2);
    int tx = threadIdx.x, ty = threadIdx.y;   // 32 x 8
    int x = blockIdx.x * 32 + tx;
#pragma unroll
    for (int i = 0; i < 4; i++)
        tile[ty + i * 8][tx] = W[(size_t)(blockIdx.y * 32 + ty + i * 8) * D_MODEL + x];
    __syncthreads();
    // 256 threads cover 32 n-rows x 16 u32-cols = 512 outputs -> 2 per thread
    int lid = ty * 32 + tx;
#pragma unroll
    for (int j = 0; j < 2; j++) {
        int o = j * 256 + lid;          // 0..511
        int n_loc = o >> 4;             // 0..31
        int kp = o & 15;                // u32 col 0..15
        float lo = tile[kp * 2][n_loc];
        float hi = tile[kp * 2 + 1][n_loc];
        int n = blockIdx.x * 32 + n_loc;
        T[(size_t)n * (D_MODEL / 2) + blockIdx.y * 16 + kp] = f2h2(lo, hi);
    }
}

// ---------------------------------------------------------------------------
// FP16 GEMM: C(MxN f32) = A(MxK f32) @ Wth(NxK fp16)^T.
// 128x128 tile, KC=32, R3-proven ldg->reg->sts double buffer.
// 256 threads = 8 warps (4 wr x 2 wc), warp tile 32x64, m16n8k16.
// smem rows padded to 20 u32 (frag LDS conflict-free: gid*20+tig distinct %32).
// ---------------------------------------------------------------------------
#define GKC 32
#define GSTAGES (D_MODEL / GKC)   // 32

__device__ __forceinline__ void gemm_f16_body(const float* __restrict__ A,
                                              const uint32_t* __restrict__ Bt,  // [n][k/2]
                                              float* __restrict__ C,
                                              int bm, int bn, int N) {
    __shared__ uint32_t As32[2][128][20];
    __shared__ uint32_t Bs32[2][128][20];

    const int tid = threadIdx.x;
    const int w = tid >> 5, lane = tid & 31;
    const int wr = w >> 1, wc = w & 1;
    const int gid = lane >> 2, tig = lane & 3;

    float acc[2][8][4] = {};

    // A producer mapping: row = tid>>1 (0..127), kh = (tid&1)*16 (f32 elems)
    const int arow = tid >> 1, akh = (tid & 1) * 16;
    float4 av[4];
    uint4 bv[2];

    auto ldg_stage = [&](int k0) {
#pragma unroll
        for (int i = 0; i < 4; i++)
            av[i] = *(const float4*)(A + (size_t)(bm + arow) * D_MODEL + k0 + akh + i * 4);
#pragma unroll
        for (int j = 0; j < 2; j++) {
            int id = j * 256 + tid;          // 0..511
            int n = id >> 2, kq = id & 3;    // n 0..127, 4 uint4 per row
            bv[j] = *(const uint4*)(Bt + (size_t)(bn + n) * (D_MODEL / 2) + k0 / 2 + kq * 4);
        }
    };
    auto sts_stage = [&](int b) {
        const float* f = (const float*)av;   // 16 consecutive k values
        uint32_t h[8];
#pragma unroll
        for (int j = 0; j < 8; j++) h[j] = f2h2(f[2 * j], f[2 * j + 1]);
        *(uint4*)&As32[b][arow][(tid & 1) * 8] = *(uint4*)&h[0];
        *(uint4*)&As32[b][arow][(tid & 1) * 8 + 4] = *(uint4*)&h[4];
#pragma unroll
        for (int j = 0; j < 2; j++) {
            int id = j * 256 + tid;
            int n = id >> 2, kq = id & 3;
            *(uint4*)&Bs32[b][n][kq * 4] = bv[j];
        }
    };

    ldg_stage(0);
    sts_stage(0);
    __syncthreads();

    int buf = 0;
    for (int ks = 0; ks < GSTAGES; ks++, buf ^= 1) {
        const bool more = (ks + 1) < GSTAGES;
        if (more) ldg_stage((ks + 1) * GKC);

#pragma unroll
        for (int kk = 0; kk < 2; kk++) {
            uint32_t af[2][4];
#pragma unroll
            for (int mt = 0; mt < 2; mt++) {
                int rb = wr * 32 + mt * 16 + gid;
                af[mt][0] = As32[buf][rb][kk * 8 + tig];
                af[mt][1] = As32[buf][rb + 8][kk * 8 + tig];
                af[mt][2] = As32[buf][rb][kk * 8 + tig + 4];
                af[mt][3] = As32[buf][rb + 8][kk * 8 + tig + 4];
            }
            uint32_t bf[8][2];
#pragma unroll
            for (int nt = 0; nt < 8; nt++) {
                int col = wc * 64 + nt * 8 + gid;
                bf[nt][0] = Bs32[buf][col][kk * 8 + tig];
                bf[nt][1] = Bs32[buf][col][kk * 8 + tig + 4];
            }
#pragma unroll
            for (int mt = 0; mt < 2; mt++)
#pragma unroll
                for (int nt = 0; nt < 8; nt++)
                    mma_f16(acc[mt][nt], af[mt], bf[nt], acc[mt][nt]);
        }

        if (more) {
            sts_stage(buf ^ 1);
            __syncthreads();
        }
    }

#pragma unroll
    for (int mt = 0; mt < 2; mt++)
#pragma unroll
        for (int nt = 0; nt < 8; nt++) {
            int row = bm + wr * 32 + mt * 16 + gid;
            int col = bn + wc * 64 + nt * 8 + 2 * tig;
            *(float2*)(C + (size_t)row * N + col) =
                make_float2(acc[mt][nt][0], acc[mt][nt][1]);
            *(float2*)(C + (size_t)(row + 8) * N + col) =
                make_float2(acc[mt][nt][2], acc[mt][nt][3]);
        }
}

__global__ __launch_bounds__(256)
void gemm_qkv_f16(const float* __restrict__ x, const uint32_t* __restrict__ Wth) {
    float* C = (blockIdx.z == 0) ? g_Q : (blockIdx.z == 1) ? g_K : g_V;
    gemm_f16_body(x, Wth + (size_t)blockIdx.z * D_MODEL * (D_MODEL / 2), C,
                  blockIdx.y * 128, blockIdx.x * 128, D_MODEL);
}

__global__ __launch_bounds__(256)
void gemm_o_f16(const float* __restrict__ Aat, const uint32_t* __restrict__ Wth,
                float* __restrict__ C) {
    gemm_f16_body(Aat, Wth + (size_t)3 * D_MODEL * (D_MODEL / 2), C,
                  blockIdx.y * 128, blockIdx.x * 128, D_MODEL);
}

// ---------------------------------------------------------------------------
// Flash attention, TF32 mma.sync (proven 583.8us version, byte-identical).
// ---------------------------------------------------------------------------
#define QS_STRIDE 68
#define VS_STRIDE 72
#define SM_Q 0
#define SM_K (128 * QS_STRIDE)
#define SM_V (SM_K + 64 * QS_STRIDE)
#define ATTN_SMEM_UINTS (SM_V + 64 * VS_STRIDE)
#define ATTN_SMEM_BYTES (ATTN_SMEM_UINTS * 4)

__global__ __launch_bounds__(256)
void attn_kernel(const float* __restrict__ Q, const float* __restrict__ K,
                 const float* __restrict__ V, float* __restrict__ O) {
    extern __shared__ uint32_t sm[];
    uint32_t* Qs = sm + SM_Q;
    uint32_t* Ps = sm + SM_Q;   // aliased: Qs dead after fragment hoist
    uint32_t* Ks = sm + SM_K;
    uint32_t* Vs = sm + SM_V;

    const int qt = blockIdx.x, h = blockIdx.y, b = blockIdx.z;
    const int tid = threadIdx.x;
    const int w = tid >> 5, lane = tid & 31;
    const int gid = lane >> 2, tig = lane & 3;

    const float* Qbase = Q + ((size_t)b * SEQ + qt * 128) * D_MODEL + h * DK;
    const float* Kbase = K + (size_t)b * SEQ * D_MODEL + h * DK;
    const float* Vbase = V + (size_t)b * SEQ * D_MODEL + h * DK;

#pragma unroll
    for (int i = 0; i < 8; i++) {
        int idx = i * 256 + tid;
        int r = idx >> 4, c = (idx & 15) * 4;
        float4 v = *(const float4*)(Qbase + (size_t)r * D_MODEL + c);
        *(uint4*)&Qs[r * QS_STRIDE + c] =
            make_uint4(f2tf(v.x), f2tf(v.y), f2tf(v.z), f2tf(v.w));
    }
    __syncthreads();

    const int r0 = w * 16 + gid;
    uint32_t qf[8][4];
#pragma unroll
    for (int kc = 0; kc < 8; kc++) {
        qf[kc][0] = Qs[r0 * QS_STRIDE + kc * 8 + tig];
        qf[kc][1] = Qs[(r0 + 8) * QS_STRIDE + kc * 8 + tig];
        qf[kc][2] = Qs[r0 * QS_STRIDE + kc * 8 + tig + 4];
        qf[kc][3] = Qs[(r0 + 8) * QS_STRIDE + kc * 8 + tig + 4];
    }

    float o[8][4] = {};
    float m0 = -1e30f, m1 = -1e30f, l0 = 0.f, l1 = 0.f;

    for (int kt = 0; kt < SEQ / 64; kt++) {
        __syncthreads();
        const float* kb = Kbase + (size_t)kt * 64 * D_MODEL;
        const float* vb = Vbase + (size_t)kt * 64 * D_MODEL;
#pragma unroll
        for (int i = 0; i < 4; i++) {
            int idx = i * 256 + tid;
            int r = idx >> 4, c = (idx & 15) * 4;
            float4 k4 = *(const float4*)(kb + (size_t)r * D_MODEL + c);
            *(uint4*)&Ks[r * QS_STRIDE + c] =
                make_uint4(f2tf(k4.x), f2tf(k4.y), f2tf(k4.z), f2tf(k4.w));
            float4 v4 = *(const float4*)(vb + (size_t)r * D_MODEL + c);
            *(uint4*)&Vs[r * VS_STRIDE + c] =
                make_uint4(f2tf(v4.x), f2tf(v4.y), f2tf(v4.z), f2tf(v4.w));
        }
        __syncthreads();

        float s[8][4] = {};
#pragma unroll
        for (int kc = 0; kc < 8; kc++) {
#pragma unroll
            for (int nt = 0; nt < 8; nt++) {
                uint32_t kf[2];
                int kvp = nt * 8 + gid;
                kf[0] = Ks[kvp * QS_STRIDE + kc * 8 + tig];
                kf[1] = Ks[kvp * QS_STRIDE + kc * 8 + tig + 4];
                mma_tf32(s[nt], qf[kc], kf, s[nt]);
            }
        }

        const float scale = 0.125f;
        float mx0 = -1e30f, mx1 = -1e30f;
#pragma unroll
        for (int nt = 0; nt < 8; nt++) {
#pragma unroll
            for (int i = 0; i < 4; i++) s[nt][i] *= scale;
            mx0 = fmaxf(mx0, fmaxf(s[nt][0], s[nt][1]));
            mx1 = fmaxf(mx1, fmaxf(s[nt][2], s[nt][3]));
        }
        mx0 = fmaxf(mx0, __shfl_xor_sync(0xffffffffu, mx0, 1));
        mx0 = fmaxf(mx0, __shfl_xor_sync(0xffffffffu, mx0, 2));
        mx1 = fmaxf(mx1, __shfl_xor_sync(0xffffffffu, mx1, 1));
        mx1 = fmaxf(mx1, __shfl_xor_sync(0xffffffffu, mx1, 2));

        float nm0 = fmaxf(m0, mx0), nm1 = fmaxf(m1, mx1);
        float corr0 = __expf(m0 - nm0), corr1 = __expf(m1 - nm1);
        m0 = nm0; m1 = nm1;

        float rs0 = 0.f, rs1 = 0.f;
#pragma unroll
        for (int nt = 0; nt < 8; nt++) {
            float p0 = __expf(s[nt][0] - nm0);
            float p1 = __expf(s[nt][1] - nm0);
            float p2 = __expf(s[nt][2] - nm1);
            float p3 = __expf(s[nt][3] - nm1);
            rs0 += p0 + p1;
            rs1 += p2 + p3;
            int col = nt * 8 + 2 * tig;
            *(uint2*)&Ps[r0 * QS_STRIDE + col] = make_uint2(f2tf(p0), f2tf(p1));
            *(uint2*)&Ps[(r0 + 8) * QS_STRIDE + col] = make_uint2(f2tf(p2), f2tf(p3));
        }
        rs0 += __shfl_xor_sync(0xffffffffu, rs0, 1);
        rs0 += __shfl_xor_sync(0xffffffffu, rs0, 2);
        rs1 += __shfl_xor_sync(0xffffffffu, rs1, 1);
        rs1 += __shfl_xor_sync(0xffffffffu, rs1, 2);
        l0 = l0 * corr0 + rs0;
        l1 = l1 * corr1 + rs1;

#pragma unroll
        for (int nt = 0; nt < 8; nt++) {
            o[nt][0] *= corr0; o[nt][1] *= corr0;
            o[nt][2] *= corr1; o[nt][3] *= corr1;
        }
        __syncwarp();

#pragma unroll
        for (int kc = 0; kc < 8; kc++) {
            uint32_t pa[4];
            pa[0] = Ps[r0 * QS_STRIDE + kc * 8 + tig];
            pa[1] = Ps[(r0 + 8) * QS_STRIDE + kc * 8 + tig];
            pa[2] = Ps[r0 * QS_STRIDE + kc * 8 + tig + 4];
            pa[3] = Ps[(r0 + 8) * QS_STRIDE + kc * 8 + tig + 4];
#pragma unroll
            for (int nt = 0; nt < 8; nt++) {
                uint32_t vf[2];
                vf[0] = Vs[(kc * 8 + tig) * VS_STRIDE + nt * 8 + gid];
                vf[1] = Vs[(kc * 8 + tig + 4) * VS_STRIDE + nt * 8 + gid];
                mma_tf32(o[nt], pa, vf, o[nt]);
            }
        }
    }

    float inv0 = 1.0f / l0, inv1 = 1.0f / l1;
    float* obase = O + ((size_t)b * SEQ + qt * 128) * D_MODEL + h * DK;
#pragma unroll
    for (int nt = 0; nt < 8; nt++) {
        int col = nt * 8 + 2 * tig;
        *(float2*)(obase + (size_t)r0 * D_MODEL + col) =
            make_float2(o[nt][0] * inv0, o[nt][1] * inv0);
        *(float2*)(obase + (size_t)(r0 + 8) * D_MODEL + col) =
            make_float2(o[nt][2] * inv1, o[nt][3] * inv1);
    }
}

// ---------------------------------------------------------------------------
extern "C" void kernel_launch(void* const* d_in, const int* in_sizes, int n_in,
                              void* d_out, int out_size) {
    const float* x  = (const float*)d_in[0];
    const float* Wq = (const float*)d_in[1];
    const float* Wk = (const float*)d_in[2];
    const float* Wv = (const float*)d_in[3];
    const float* Wo = (const float*)d_in[4];
    float* out = (float*)d_out;

    float *Qp, *Kp, *Vp, *Ap;
    uint32_t* Wth;
    cudaGetSymbolAddress((void**)&Qp, g_Q);
    cudaGetSymbolAddress((void**)&Kp, g_K);
    cudaGetSymbolAddress((void**)&Vp, g_V);
    cudaGetSymbolAddress((void**)&Ap, g_att);
    cudaGetSymbolAddress((void**)&Wth, g_Wth);

    // W^T -> fp16 (coalesced both sides via smem tile)
    transpose_h2_kernel<<<dim3(32, 32, 4), dim3(32, 8)>>>(Wq, Wk, Wv, Wo, Wth);

    // QKV projections (fp16 tensor path)
    gemm_qkv_f16<<<dim3(8, 32, 3), 256>>>(x, Wth);

    // Attention (proven tf32 version)
    cudaFuncSetAttribute(attn_kernel, cudaFuncAttributeMaxDynamicSharedMemorySize,
                         ATTN_SMEM_BYTES);
    attn_kernel<<<dim3(SEQ / 128, NHEAD, BATCH), 256, ATTN_SMEM_BYTES>>>(Qp, Kp, Vp, Ap);

    // Output projection (fp16 tensor path)
    gemm_o_f16<<<dim3(8, 32, 1), 256>>>(Ap, Wth, out);
}